// round 14
// baseline (speedup 1.0000x reference)
#include <cuda_runtime.h>
#include <cuda_fp16.h>
#include <cstdint>

#define BB   8
#define CC   256
#define NN   16384
#define LOG2E 1.4426950408889634f

// Scratch (device-global; no allocations allowed)
__device__ __half  g_Kh[(size_t)BB * 256 * NN];  // exp2(K') fp16 (64 MB)
__device__ __half  g_Xh[(size_t)BB * 256 * NN];  // x rounded to fp16 (64 MB)
__device__ float    g_s[BB * 256];               // softmax denominators
__device__ float    g_T[BB * 256 * 256];         // T = expK @ x^T (f32, 2 MB)
__device__ uint32_t g_Wh[256 * 128];             // Wk*log2e packed half2

// ---------------------------------------------------------------------------
// fp16 mma.sync m16n8k16 (fp32 accumulate)
// ---------------------------------------------------------------------------
__device__ __forceinline__ void mma_f16(float* d, const uint32_t* a,
                                        const uint32_t* b) {
    asm volatile(
        "mma.sync.aligned.m16n8k16.row.col.f32.f16.f16.f32 "
        "{%0,%1,%2,%3}, {%4,%5,%6,%7}, {%8,%9}, {%0,%1,%2,%3};"
        : "+f"(d[0]), "+f"(d[1]), "+f"(d[2]), "+f"(d[3])
        : "r"(a[0]), "r"(a[1]), "r"(a[2]), "r"(a[3]), "r"(b[0]), "r"(b[1]));
}

__device__ __forceinline__ uint32_t pack_h2(float lo, float hi) {
    __half2 h = __floats2half2_rn(lo, hi);
    return *(uint32_t*)&h;
}

__device__ __forceinline__ float ex2f(float x) {
    float r;
    asm("ex2.approx.f32 %0, %1;" : "=f"(r) : "f"(x));
    return r;
}

#define CPA16(dst, src) \
    asm volatile("cp.async.cg.shared.global [%0], [%1], 16;" \
                 :: "r"(dst), "l"(src) : "memory")
#define CPA_COMMIT() asm volatile("cp.async.commit_group;" ::: "memory")
#define CPA_WAIT1()  asm volatile("cp.async.wait_group 1;" ::: "memory")

// ---------------------------------------------------------------------------
// K0: zero g_s + g_T; pack Wk*log2e into half2 pairs g_Wh
// ---------------------------------------------------------------------------
__global__ void k0_prep(const float* __restrict__ Wk) {
    int i = blockIdx.x * 256 + threadIdx.x;
    if (i < BB * 256) g_s[i] = 0.0f;
    if (i < BB * 256 * 256) g_T[i] = 0.0f;
    if (i < 256 * 128) {
        int r = i >> 7, c = (i & 127) * 2;
        const float* W = &Wk[r * 256 + c];
        g_Wh[i] = pack_h2(W[0] * LOG2E, W[1] * LOG2E);
    }
}

// ---------------------------------------------------------------------------
// K1: K = Wk @ x (log2 domain); exp2 + rowsum fused; dumps fp16 x to g_Xh.
// One CTA per (n-tile, b). B = x tile (256 ch x 128 n) gathered ONCE to
// fp16 smem [n][k] stride 132; A = Wk streamed via 3-stage cp.async ring
// over 16 chunks (2 m-tiles x 8). grid (128 n, 8 b), 256 thr, occ 2.
// ---------------------------------------------------------------------------
#define BSTR      132                            // u32 per B n-row
#define K1_B_B    (128 * BSTR * 4)               // 67584
#define ASTG_U    (128 * 20)                     // u32 per A stage
#define K1_SMEM   (K1_B_B + 3 * ASTG_U * 4)      // 98304 (96 KB)

__global__ void __launch_bounds__(256, 2)
k1_gemm(const float* __restrict__ x, const float* __restrict__ bk) {
    extern __shared__ char sm1[];
    const uint32_t smbase = (uint32_t)__cvta_generic_to_shared(sm1);

    const int tid  = threadIdx.x;
    const int wid  = tid >> 5;
    const int lane = tid & 31;
    const int lr   = lane >> 2, lc = lane & 3;
    const int wm   = (wid & 3) * 32;
    const int wn   = (wid >> 2) * 64;

    const int n0 = blockIdx.x * 128;
    const int b  = blockIdx.y;

    uint32_t*       sBu  = (uint32_t*)sm1;
    const uint32_t* ring = (const uint32_t*)(sm1 + K1_B_B);
    const uint32_t  ringb = smbase + K1_B_B;

    auto a_prefetch = [&](int st, int g) {
        const size_t off = (size_t)(g >> 3) * 16384 + (size_t)(g & 7) * 16;
        const uint32_t dst = ringb + (uint32_t)(st * ASTG_U * 4);
        #pragma unroll
        for (int p = 0; p < 2; ++p) {
            const int idx = tid + p * 256;
            const int row = idx >> 2, qu = (idx & 3) * 4;
            CPA16(dst + (uint32_t)(row * 20 + qu) * 4,
                  g_Wh + off + (size_t)row * 128 + qu);
        }
    };

    a_prefetch(0, 0); CPA_COMMIT();
    a_prefetch(1, 1); CPA_COMMIT();

    // ---- B prologue: gather x (256 ch x 128 n) -> fp16 smem + g_Xh ----
    for (int ic8 = 0; ic8 < 8; ++ic8) {
        const int ch0 = ic8 * 32 + 4 * wid;
        const float* Xc = x + (size_t)b * CC * NN + (size_t)ch0 * NN + n0;
        float v[16];
        #pragma unroll
        for (int i2 = 0; i2 < 4; ++i2) {
            const int nl = i2 * 32 + lane;
            v[i2 * 4 + 0] = Xc[nl];
            v[i2 * 4 + 1] = Xc[(size_t)NN + nl];
            v[i2 * 4 + 2] = Xc[2 * (size_t)NN + nl];
            v[i2 * 4 + 3] = Xc[3 * (size_t)NN + nl];
        }
        #pragma unroll
        for (int i2 = 0; i2 < 4; ++i2) {
            const int nl = i2 * 32 + lane;
            uint32_t* d = sBu + nl * BSTR + ic8 * 16 + 2 * wid;
            d[0] = pack_h2(v[i2 * 4 + 0], v[i2 * 4 + 1]);
            d[1] = pack_h2(v[i2 * 4 + 2], v[i2 * 4 + 3]);
            #pragma unroll
            for (int j = 0; j < 4; ++j)
                g_Xh[((size_t)b * 256 + ch0 + j) * NN + n0 + nl] =
                    __float2half_rn(v[i2 * 4 + j]);
        }
    }
    __syncthreads();

    float acc[2][8][4];
    #pragma unroll
    for (int i = 0; i < 2; ++i)
        #pragma unroll
        for (int j = 0; j < 8; ++j)
            #pragma unroll
            for (int t = 0; t < 4; ++t) acc[i][j][t] = 0.0f;

    for (int g = 0; g < 16; ++g) {
        CPA_WAIT1();
        __syncthreads();
        const uint32_t* sAu = ring + (g % 3) * ASTG_U;
        const int bcol = (g & 7) * 16;

        #pragma unroll
        for (int ks = 0; ks < 2; ++ks) {
            uint32_t a[2][4], bf[8][2];
            #pragma unroll
            for (int i = 0; i < 2; ++i) {
                const int base = (wm + i * 16 + lr) * 20 + ks * 8 + lc;
                a[i][0] = sAu[base];
                a[i][1] = sAu[base + 8 * 20];
                a[i][2] = sAu[base + 4];
                a[i][3] = sAu[base + 8 * 20 + 4];
            }
            #pragma unroll
            for (int j = 0; j < 8; ++j) {
                const int base = (wn + j * 8 + lr) * BSTR + bcol + ks * 8 + lc;
                bf[j][0] = sBu[base];
                bf[j][1] = sBu[base + 4];
            }
            #pragma unroll
            for (int i = 0; i < 2; ++i)
                #pragma unroll
                for (int j = 0; j < 8; ++j) mma_f16(acc[i][j], a[i], bf[j]);
        }

        if (g + 2 < 16) a_prefetch((g + 2) % 3, g + 2);
        CPA_COMMIT();

        if ((g & 7) == 7) {
            const int mrow0 = (g >> 3) * 128;
            float rs[2][2] = {{0.f, 0.f}, {0.f, 0.f}};
            #pragma unroll
            for (int i = 0; i < 2; ++i) {
                const int ch0 = mrow0 + wm + i * 16 + lr;
                const int ch1 = ch0 + 8;
                const float b0 = bk[ch0] * LOG2E, b1 = bk[ch1] * LOG2E;
                uint32_t* r0 = (uint32_t*)(g_Kh + ((size_t)b * 256 + ch0) * NN
                                           + n0 + wn + 2 * lc);
                uint32_t* r1 = (uint32_t*)(g_Kh + ((size_t)b * 256 + ch1) * NN
                                           + n0 + wn + 2 * lc);
                #pragma unroll
                for (int j = 0; j < 8; ++j) {
                    float v0 = ex2f(acc[i][j][0] + b0);
                    float v1 = ex2f(acc[i][j][1] + b0);
                    float v2 = ex2f(acc[i][j][2] + b1);
                    float v3 = ex2f(acc[i][j][3] + b1);
                    __half2 h0 = __floats2half2_rn(v0, v1);
                    __half2 h1 = __floats2half2_rn(v2, v3);
                    float2 f0 = __half22float2(h0);
                    float2 f1 = __half22float2(h1);
                    rs[i][0] += f0.x + f0.y;
                    rs[i][1] += f1.x + f1.y;
                    r0[j * 4] = *(uint32_t*)&h0;
                    r1[j * 4] = *(uint32_t*)&h1;
                    #pragma unroll
                    for (int t = 0; t < 4; ++t) acc[i][j][t] = 0.0f;
                }
            }
            #pragma unroll
            for (int i = 0; i < 2; ++i)
                #pragma unroll
                for (int h = 0; h < 2; ++h) {
                    float v = rs[i][h];
                    v += __shfl_xor_sync(0xffffffffu, v, 1);
                    v += __shfl_xor_sync(0xffffffffu, v, 2);
                    if (lc == 0) {
                        int ch = mrow0 + wm + i * 16 + lr + h * 8;
                        atomicAdd(&g_s[b * 256 + ch], v);
                    }
                }
        }
    }
}

// ---------------------------------------------------------------------------
// K3: T[k][c] = sum_n expK[k,n] * xh[c,n]  (fp16 operands, f32 acc).
// 256 thr, warp tile 32x64, CTA 128x128, chunk 32 spatial, 3-stage ring,
// contraction split 8 ways, atomicAdd into g_T. grid (4 tiles, 8, 8).
// ---------------------------------------------------------------------------
#define SA3U      20
#define K3_T_B    (128 * SA3U * 4)              // 10240 per tile
#define K3_STG    (2 * K3_T_B)                  // 20480 bytes/stage
#define K3_SMEM   (3 * K3_STG)                  // 61440

__device__ __forceinline__ void k3_prefetch(uint32_t smbase, int st,
                                            const __half* Kb, const __half* Xb,
                                            int c0, int tid) {
    const uint32_t sA = smbase + (uint32_t)(st * K3_STG);
    const uint32_t sB = sA + K3_T_B;
    #pragma unroll
    for (int p = 0; p < 2; ++p) {
        const int idx = tid + p * 256;
        const int row = idx >> 2, qu = (idx & 3) * 4;
        const uint32_t off = (uint32_t)(row * SA3U + qu) * 4;
        CPA16(sA + off, Kb + (size_t)row * NN + c0 + qu * 2);
        CPA16(sB + off, Xb + (size_t)row * NN + c0 + qu * 2);
    }
}

__global__ void __launch_bounds__(256, 2)
k3_tmat() {
    extern __shared__ char sm3[];
    const uint32_t smbase = (uint32_t)__cvta_generic_to_shared(sm3);

    const int tid  = threadIdx.x;
    const int wid  = tid >> 5;
    const int lane = tid & 31;
    const int lr   = lane >> 2, lc = lane & 3;
    const int wm   = (wid & 3) * 32;
    const int wn   = (wid >> 2) * 64;

    const int km0 = (blockIdx.x & 1) * 128;
    const int cm0 = (blockIdx.x >> 1) * 128;
    const int nb  = blockIdx.y * 2048;
    const int b   = blockIdx.z;

    const __half* Kb = g_Kh + ((size_t)b * 256 + km0) * NN + nb;
    const __half* Xb = g_Xh + ((size_t)b * 256 + cm0) * NN + nb;

    float acc[2][8][4];
    #pragma unroll
    for (int i = 0; i < 2; ++i)
        #pragma unroll
        for (int j = 0; j < 8; ++j)
            #pragma unroll
            for (int t = 0; t < 4; ++t) acc[i][j][t] = 0.0f;

    k3_prefetch(smbase, 0, Kb, Xb, 0, tid);
    CPA_COMMIT();
    k3_prefetch(smbase, 1, Kb, Xb, 32, tid);
    CPA_COMMIT();

    for (int ic = 0; ic < 64; ++ic) {
        CPA_WAIT1();
        __syncthreads();
        const uint32_t* sAu = (const uint32_t*)(sm3 + (ic % 3) * K3_STG);
        const uint32_t* sBu = (const uint32_t*)(sm3 + (ic % 3) * K3_STG + K3_T_B);

        #pragma unroll
        for (int ks = 0; ks < 2; ++ks) {
            uint32_t a[2][4], bf[8][2];
            #pragma unroll
            for (int i = 0; i < 2; ++i) {
                const int base = (wm + i * 16 + lr) * SA3U + ks * 8 + lc;
                a[i][0] = sAu[base];
                a[i][1] = sAu[base + 8 * SA3U];
                a[i][2] = sAu[base + 4];
                a[i][3] = sAu[base + 8 * SA3U + 4];
            }
            #pragma unroll
            for (int j = 0; j < 8; ++j) {
                const int base = (wn + j * 8 + lr) * SA3U + ks * 8 + lc;
                bf[j][0] = sBu[base];
                bf[j][1] = sBu[base + 4];
            }
            #pragma unroll
            for (int i = 0; i < 2; ++i)
                #pragma unroll
                for (int j = 0; j < 8; ++j) mma_f16(acc[i][j], a[i], bf[j]);
        }

        if (ic + 2 < 64)
            k3_prefetch(smbase, (ic + 2) % 3, Kb, Xb, (ic + 2) * 32, tid);
        CPA_COMMIT();
    }

    #pragma unroll
    for (int i = 0; i < 2; ++i) {
        const int k0r = km0 + wm + i * 16 + lr;
        const int k1r = k0r + 8;
        float* r0 = g_T + ((size_t)b * 256 + k0r) * 256 + cm0 + wn + 2 * lc;
        float* r1 = g_T + ((size_t)b * 256 + k1r) * 256 + cm0 + wn + 2 * lc;
        #pragma unroll
        for (int j = 0; j < 8; ++j) {
            atomicAdd(r0 + j * 8,     acc[i][j][0]);
            atomicAdd(r0 + j * 8 + 1, acc[i][j][1]);
            atomicAdd(r1 + j * 8,     acc[i][j][2]);
            atomicAdd(r1 + j * 8 + 1, acc[i][j][3]);
        }
    }
}

// ---------------------------------------------------------------------------
// K4: out[b,k,v] = (1/s[b,k]) * sum_c T[b,k,c] * Wv[v,c] + bv[v]
// fp32 GEMM, 32x64 (k x v) tiles -> grid (32, 8) = 256 CTAs (4x R13
// parallelism), 256 thr, 2x4 micro-tile, chunks of 32 c.
// ---------------------------------------------------------------------------
__global__ void __launch_bounds__(256)
k4_out(const float* __restrict__ Wv, const float* __restrict__ bv,
       float* __restrict__ out) {
    __shared__ float Ts[32][36];   // [c][k]
    __shared__ float Ws[32][68];   // [c][v]

    const int tid = threadIdx.x;
    const int tx = tid & 15, ty = tid >> 4;      // tx -> v (4 each), ty -> k (2)
    const int k0t = (blockIdx.x & 7) * 32;
    const int v0t = (blockIdx.x >> 3) * 64;
    const int b   = blockIdx.y;

    float acc[2][4];
    #pragma unroll
    for (int i = 0; i < 2; ++i)
        #pragma unroll
        for (int j = 0; j < 4; ++j) acc[i][j] = 0.0f;

    for (int c0 = 0; c0 < 256; c0 += 32) {
        {   // T tile: 32 k-rows x 32 c (one float4 per thread)
            const int row = tid >> 3, q = (tid & 7) * 4;
            float4 tv = *(const float4*)(g_T + ((size_t)b * 256 + k0t + row) * 256
                                         + c0 + q);
            Ts[q + 0][row] = tv.x; Ts[q + 1][row] = tv.y;
            Ts[q + 2][row] = tv.z; Ts[q + 3][row] = tv.w;
        }
        #pragma unroll
        for (int p = 0; p < 2; ++p) {   // W tile: 64 v-rows x 32 c
            const int idx = tid + p * 256;
            const int row = idx >> 3, q = (idx & 7) * 4;
            float4 wv = *(const float4*)(Wv + (size_t)(v0t + row) * 256 + c0 + q);
            Ws[q + 0][row] = wv.x; Ws[q + 1][row] = wv.y;
            Ws[q + 2][row] = wv.z; Ws[q + 3][row] = wv.w;
        }
        __syncthreads();

        #pragma unroll
        for (int cc = 0; cc < 32; ++cc) {
            float a0 = Ts[cc][ty * 2], a1 = Ts[cc][ty * 2 + 1];
            float4 w4 = *(const float4*)&Ws[cc][tx * 4];
            acc[0][0] += a0 * w4.x; acc[0][1] += a0 * w4.y;
            acc[0][2] += a0 * w4.z; acc[0][3] += a0 * w4.w;
            acc[1][0] += a1 * w4.x; acc[1][1] += a1 * w4.y;
            acc[1][2] += a1 * w4.z; acc[1][3] += a1 * w4.w;
        }
        __syncthreads();
    }

    #pragma unroll
    for (int i = 0; i < 2; ++i) {
        const int k = k0t + ty * 2 + i;
        const float inv = 1.0f / g_s[b * 256 + k];
        float* dst = out + ((size_t)b * 256 + k) * 256 + v0t + tx * 4;
        #pragma unroll
        for (int j = 0; j < 4; ++j)
            dst[j] = acc[i][j] * inv + bv[v0t + tx * 4 + j];
    }
}

// ---------------------------------------------------------------------------
// Launch
// ---------------------------------------------------------------------------
extern "C" void kernel_launch(void* const* d_in, const int* in_sizes, int n_in,
                              void* d_out, int out_size) {
    const float* x  = (const float*)d_in[0];
    const float* Wk = (const float*)d_in[1];
    const float* bk = (const float*)d_in[2];
    const float* Wv = (const float*)d_in[3];
    const float* bv = (const float*)d_in[4];
    float* out = (float*)d_out;

    cudaFuncSetAttribute(k1_gemm, cudaFuncAttributeMaxDynamicSharedMemorySize,
                         K1_SMEM);
    cudaFuncSetAttribute(k3_tmat, cudaFuncAttributeMaxDynamicSharedMemorySize,
                         K3_SMEM);

    k0_prep<<<(BB * 256 * 256 + 255) / 256, 256>>>(Wk);

    dim3 g1(128, BB);
    k1_gemm<<<g1, 256, K1_SMEM>>>(x, bk);

    dim3 g3(4, 8, BB);
    k3_tmat<<<g3, 256, K3_SMEM>>>();

    dim3 g4(32, BB);
    k4_out<<<g4, 256>>>(Wv, bv, out);
}

// round 16
// speedup vs baseline: 1.0261x; 1.0261x over previous
#include <cuda_runtime.h>
#include <cuda_fp16.h>
#include <cstdint>

#define BB   8
#define CC   256
#define NN   16384
#define LOG2E 1.4426950408889634f

// Scratch (device-global; no allocations allowed)
__device__ __half  g_Kh[(size_t)BB * 256 * NN];  // exp2(K') fp16 (64 MB)
__device__ __half  g_Xh[(size_t)BB * 256 * NN];  // x rounded to fp16 (64 MB)
__device__ float    g_s[BB * 256];               // softmax denominators
__device__ float    g_T[BB * 256 * 256];         // T = expK @ x^T (f32, 2 MB)
__device__ uint32_t g_Wh[256 * 128];             // Wk*log2e packed half2

// ---------------------------------------------------------------------------
// fp16 mma.sync m16n8k16 (fp32 accumulate)
// ---------------------------------------------------------------------------
__device__ __forceinline__ void mma_f16(float* d, const uint32_t* a,
                                        const uint32_t* b) {
    asm volatile(
        "mma.sync.aligned.m16n8k16.row.col.f32.f16.f16.f32 "
        "{%0,%1,%2,%3}, {%4,%5,%6,%7}, {%8,%9}, {%0,%1,%2,%3};"
        : "+f"(d[0]), "+f"(d[1]), "+f"(d[2]), "+f"(d[3])
        : "r"(a[0]), "r"(a[1]), "r"(a[2]), "r"(a[3]), "r"(b[0]), "r"(b[1]));
}

__device__ __forceinline__ uint32_t pack_h2(float lo, float hi) {
    __half2 h = __floats2half2_rn(lo, hi);
    return *(uint32_t*)&h;
}

__device__ __forceinline__ float ex2f(float x) {
    float r;
    asm("ex2.approx.f32 %0, %1;" : "=f"(r) : "f"(x));
    return r;
}

// Packed f32x2 FMA (sm_100+): 2 fp32 FMA per issue.
__device__ __forceinline__ void fma2(unsigned long long& d,
                                     unsigned long long a,
                                     unsigned long long b) {
    asm("fma.rn.f32x2 %0, %1, %2, %0;" : "+l"(d) : "l"(a), "l"(b));
}
__device__ __forceinline__ unsigned long long dup2(float x) {
    unsigned long long r;
    asm("mov.b64 %0, {%1, %1};" : "=l"(r) : "f"(x));
    return r;
}
__device__ __forceinline__ unsigned long long pk2(float lo, float hi) {
    unsigned long long r;
    asm("mov.b64 %0, {%1, %2};" : "=l"(r) : "f"(lo), "f"(hi));
    return r;
}
__device__ __forceinline__ float2 unpk2(unsigned long long v) {
    float2 p;
    asm("mov.b64 {%0, %1}, %2;" : "=f"(p.x), "=f"(p.y) : "l"(v));
    return p;
}

#define CPA16(dst, src) \
    asm volatile("cp.async.cg.shared.global [%0], [%1], 16;" \
                 :: "r"(dst), "l"(src) : "memory")
#define CPA_COMMIT() asm volatile("cp.async.commit_group;" ::: "memory")
#define CPA_WAIT1()  asm volatile("cp.async.wait_group 1;" ::: "memory")

// ---------------------------------------------------------------------------
// K0: zero g_s + g_T (float4); pack Wk*log2e into half2 pairs g_Wh
// grid 512 x 256 thr.
// ---------------------------------------------------------------------------
__global__ void k0_prep(const float* __restrict__ Wk) {
    int i = blockIdx.x * 256 + threadIdx.x;      // < 131072
    ((float4*)g_T)[i] = make_float4(0.f, 0.f, 0.f, 0.f);
    if (i < BB * 256) g_s[i] = 0.0f;
    if (i < 256 * 128) {
        int r = i >> 7, c = (i & 127) * 2;
        const float* W = &Wk[r * 256 + c];
        g_Wh[i] = pack_h2(W[0] * LOG2E, W[1] * LOG2E);
    }
}

// ---------------------------------------------------------------------------
// K1: K = Wk @ x (log2 domain); exp2 + rowsum fused; dumps fp16 x to g_Xh.
// (unchanged from R13) grid (128 n, 8 b), 256 thr, occ 2.
// ---------------------------------------------------------------------------
#define BSTR      132                            // u32 per B n-row
#define K1_B_B    (128 * BSTR * 4)               // 67584
#define ASTG_U    (128 * 20)                     // u32 per A stage
#define K1_SMEM   (K1_B_B + 3 * ASTG_U * 4)      // 98304 (96 KB)

__global__ void __launch_bounds__(256, 2)
k1_gemm(const float* __restrict__ x, const float* __restrict__ bk) {
    extern __shared__ char sm1[];
    const uint32_t smbase = (uint32_t)__cvta_generic_to_shared(sm1);

    const int tid  = threadIdx.x;
    const int wid  = tid >> 5;
    const int lane = tid & 31;
    const int lr   = lane >> 2, lc = lane & 3;
    const int wm   = (wid & 3) * 32;
    const int wn   = (wid >> 2) * 64;

    const int n0 = blockIdx.x * 128;
    const int b  = blockIdx.y;

    uint32_t*       sBu  = (uint32_t*)sm1;
    const uint32_t* ring = (const uint32_t*)(sm1 + K1_B_B);
    const uint32_t  ringb = smbase + K1_B_B;

    auto a_prefetch = [&](int st, int g) {
        const size_t off = (size_t)(g >> 3) * 16384 + (size_t)(g & 7) * 16;
        const uint32_t dst = ringb + (uint32_t)(st * ASTG_U * 4);
        #pragma unroll
        for (int p = 0; p < 2; ++p) {
            const int idx = tid + p * 256;
            const int row = idx >> 2, qu = (idx & 3) * 4;
            CPA16(dst + (uint32_t)(row * 20 + qu) * 4,
                  g_Wh + off + (size_t)row * 128 + qu);
        }
    };

    a_prefetch(0, 0); CPA_COMMIT();
    a_prefetch(1, 1); CPA_COMMIT();

    for (int ic8 = 0; ic8 < 8; ++ic8) {
        const int ch0 = ic8 * 32 + 4 * wid;
        const float* Xc = x + (size_t)b * CC * NN + (size_t)ch0 * NN + n0;
        float v[16];
        #pragma unroll
        for (int i2 = 0; i2 < 4; ++i2) {
            const int nl = i2 * 32 + lane;
            v[i2 * 4 + 0] = Xc[nl];
            v[i2 * 4 + 1] = Xc[(size_t)NN + nl];
            v[i2 * 4 + 2] = Xc[2 * (size_t)NN + nl];
            v[i2 * 4 + 3] = Xc[3 * (size_t)NN + nl];
        }
        #pragma unroll
        for (int i2 = 0; i2 < 4; ++i2) {
            const int nl = i2 * 32 + lane;
            uint32_t* d = sBu + nl * BSTR + ic8 * 16 + 2 * wid;
            d[0] = pack_h2(v[i2 * 4 + 0], v[i2 * 4 + 1]);
            d[1] = pack_h2(v[i2 * 4 + 2], v[i2 * 4 + 3]);
            #pragma unroll
            for (int j = 0; j < 4; ++j)
                g_Xh[((size_t)b * 256 + ch0 + j) * NN + n0 + nl] =
                    __float2half_rn(v[i2 * 4 + j]);
        }
    }
    __syncthreads();

    float acc[2][8][4];
    #pragma unroll
    for (int i = 0; i < 2; ++i)
        #pragma unroll
        for (int j = 0; j < 8; ++j)
            #pragma unroll
            for (int t = 0; t < 4; ++t) acc[i][j][t] = 0.0f;

    for (int g = 0; g < 16; ++g) {
        CPA_WAIT1();
        __syncthreads();
        const uint32_t* sAu = ring + (g % 3) * ASTG_U;
        const int bcol = (g & 7) * 16;

        #pragma unroll
        for (int ks = 0; ks < 2; ++ks) {
            uint32_t a[2][4], bf[8][2];
            #pragma unroll
            for (int i = 0; i < 2; ++i) {
                const int base = (wm + i * 16 + lr) * 20 + ks * 8 + lc;
                a[i][0] = sAu[base];
                a[i][1] = sAu[base + 8 * 20];
                a[i][2] = sAu[base + 4];
                a[i][3] = sAu[base + 8 * 20 + 4];
            }
            #pragma unroll
            for (int j = 0; j < 8; ++j) {
                const int base = (wn + j * 8 + lr) * BSTR + bcol + ks * 8 + lc;
                bf[j][0] = sBu[base];
                bf[j][1] = sBu[base + 4];
            }
            #pragma unroll
            for (int i = 0; i < 2; ++i)
                #pragma unroll
                for (int j = 0; j < 8; ++j) mma_f16(acc[i][j], a[i], bf[j]);
        }

        if (g + 2 < 16) a_prefetch((g + 2) % 3, g + 2);
        CPA_COMMIT();

        if ((g & 7) == 7) {
            const int mrow0 = (g >> 3) * 128;
            float rs[2][2] = {{0.f, 0.f}, {0.f, 0.f}};
            #pragma unroll
            for (int i = 0; i < 2; ++i) {
                const int ch0 = mrow0 + wm + i * 16 + lr;
                const int ch1 = ch0 + 8;
                const float b0 = bk[ch0] * LOG2E, b1 = bk[ch1] * LOG2E;
                uint32_t* r0 = (uint32_t*)(g_Kh + ((size_t)b * 256 + ch0) * NN
                                           + n0 + wn + 2 * lc);
                uint32_t* r1 = (uint32_t*)(g_Kh + ((size_t)b * 256 + ch1) * NN
                                           + n0 + wn + 2 * lc);
                #pragma unroll
                for (int j = 0; j < 8; ++j) {
                    float v0 = ex2f(acc[i][j][0] + b0);
                    float v1 = ex2f(acc[i][j][1] + b0);
                    float v2 = ex2f(acc[i][j][2] + b1);
                    float v3 = ex2f(acc[i][j][3] + b1);
                    __half2 h0 = __floats2half2_rn(v0, v1);
                    __half2 h1 = __floats2half2_rn(v2, v3);
                    float2 f0 = __half22float2(h0);
                    float2 f1 = __half22float2(h1);
                    rs[i][0] += f0.x + f0.y;
                    rs[i][1] += f1.x + f1.y;
                    r0[j * 4] = *(uint32_t*)&h0;
                    r1[j * 4] = *(uint32_t*)&h1;
                    #pragma unroll
                    for (int t = 0; t < 4; ++t) acc[i][j][t] = 0.0f;
                }
            }
            #pragma unroll
            for (int i = 0; i < 2; ++i)
                #pragma unroll
                for (int h = 0; h < 2; ++h) {
                    float v = rs[i][h];
                    v += __shfl_xor_sync(0xffffffffu, v, 1);
                    v += __shfl_xor_sync(0xffffffffu, v, 2);
                    if (lc == 0) {
                        int ch = mrow0 + wm + i * 16 + lr + h * 8;
                        atomicAdd(&g_s[b * 256 + ch], v);
                    }
                }
        }
    }
}

// ---------------------------------------------------------------------------
// K3: T[k][c] = sum_n expK[k,n] * xh[c,n]  (unchanged from R13)
// ---------------------------------------------------------------------------
#define SA3U      20
#define K3_T_B    (128 * SA3U * 4)              // 10240 per tile
#define K3_STG    (2 * K3_T_B)                  // 20480 bytes/stage
#define K3_SMEM   (3 * K3_STG)                  // 61440

__device__ __forceinline__ void k3_prefetch(uint32_t smbase, int st,
                                            const __half* Kb, const __half* Xb,
                                            int c0, int tid) {
    const uint32_t sA = smbase + (uint32_t)(st * K3_STG);
    const uint32_t sB = sA + K3_T_B;
    #pragma unroll
    for (int p = 0; p < 2; ++p) {
        const int idx = tid + p * 256;
        const int row = idx >> 2, qu = (idx & 3) * 4;
        const uint32_t off = (uint32_t)(row * SA3U + qu) * 4;
        CPA16(sA + off, Kb + (size_t)row * NN + c0 + qu * 2);
        CPA16(sB + off, Xb + (size_t)row * NN + c0 + qu * 2);
    }
}

__global__ void __launch_bounds__(256, 2)
k3_tmat() {
    extern __shared__ char sm3[];
    const uint32_t smbase = (uint32_t)__cvta_generic_to_shared(sm3);

    const int tid  = threadIdx.x;
    const int wid  = tid >> 5;
    const int lane = tid & 31;
    const int lr   = lane >> 2, lc = lane & 3;
    const int wm   = (wid & 3) * 32;
    const int wn   = (wid >> 2) * 64;

    const int km0 = (blockIdx.x & 1) * 128;
    const int cm0 = (blockIdx.x >> 1) * 128;
    const int nb  = blockIdx.y * 2048;
    const int b   = blockIdx.z;

    const __half* Kb = g_Kh + ((size_t)b * 256 + km0) * NN + nb;
    const __half* Xb = g_Xh + ((size_t)b * 256 + cm0) * NN + nb;

    float acc[2][8][4];
    #pragma unroll
    for (int i = 0; i < 2; ++i)
        #pragma unroll
        for (int j = 0; j < 8; ++j)
            #pragma unroll
            for (int t = 0; t < 4; ++t) acc[i][j][t] = 0.0f;

    k3_prefetch(smbase, 0, Kb, Xb, 0, tid);
    CPA_COMMIT();
    k3_prefetch(smbase, 1, Kb, Xb, 32, tid);
    CPA_COMMIT();

    for (int ic = 0; ic < 64; ++ic) {
        CPA_WAIT1();
        __syncthreads();
        const uint32_t* sAu = (const uint32_t*)(sm3 + (ic % 3) * K3_STG);
        const uint32_t* sBu = (const uint32_t*)(sm3 + (ic % 3) * K3_STG + K3_T_B);

        #pragma unroll
        for (int ks = 0; ks < 2; ++ks) {
            uint32_t a[2][4], bf[8][2];
            #pragma unroll
            for (int i = 0; i < 2; ++i) {
                const int base = (wm + i * 16 + lr) * SA3U + ks * 8 + lc;
                a[i][0] = sAu[base];
                a[i][1] = sAu[base + 8 * SA3U];
                a[i][2] = sAu[base + 4];
                a[i][3] = sAu[base + 8 * SA3U + 4];
            }
            #pragma unroll
            for (int j = 0; j < 8; ++j) {
                const int base = (wn + j * 8 + lr) * SA3U + ks * 8 + lc;
                bf[j][0] = sBu[base];
                bf[j][1] = sBu[base + 4];
            }
            #pragma unroll
            for (int i = 0; i < 2; ++i)
                #pragma unroll
                for (int j = 0; j < 8; ++j) mma_f16(acc[i][j], a[i], bf[j]);
        }

        if (ic + 2 < 64)
            k3_prefetch(smbase, (ic + 2) % 3, Kb, Xb, (ic + 2) * 32, tid);
        CPA_COMMIT();
    }

    #pragma unroll
    for (int i = 0; i < 2; ++i) {
        const int k0r = km0 + wm + i * 16 + lr;
        const int k1r = k0r + 8;
        float* r0 = g_T + ((size_t)b * 256 + k0r) * 256 + cm0 + wn + 2 * lc;
        float* r1 = g_T + ((size_t)b * 256 + k1r) * 256 + cm0 + wn + 2 * lc;
        #pragma unroll
        for (int j = 0; j < 8; ++j) {
            atomicAdd(r0 + j * 8,     acc[i][j][0]);
            atomicAdd(r0 + j * 8 + 1, acc[i][j][1]);
            atomicAdd(r1 + j * 8,     acc[i][j][2]);
            atomicAdd(r1 + j * 8 + 1, acc[i][j][3]);
        }
    }
}

// ---------------------------------------------------------------------------
// K4: out[b,k,v] = (1/s[b,k]) * sum_c T[b,k,c] * Wv[v,c] + bv[v]
// 64x64 tiles (grid 128), double-buffered smem (stride 68 BOTH tiles),
// register prefetch, fma.rn.f32x2 inner loop. 1 sync/chunk.
// ---------------------------------------------------------------------------
#define K4_TILE 2176                 // 32 c x 68 (64 rows + pad)
#define K4_STGF (2 * K4_TILE)        // 4352 floats per stage

__global__ void __launch_bounds__(256)
k4_out(const float* __restrict__ Wv, const float* __restrict__ bv,
       float* __restrict__ out) {
    __shared__ float sm4[2 * K4_STGF];   // 34816 B

    const int tid = threadIdx.x;
    const int tx = tid & 15, ty = tid >> 4;
    const int k0t = (blockIdx.x & 3) * 64;
    const int v0t = (blockIdx.x >> 2) * 64;
    const int b   = blockIdx.y;

    unsigned long long acc[4][2];
    #pragma unroll
    for (int i = 0; i < 4; ++i) { acc[i][0] = 0ULL; acc[i][1] = 0ULL; }

    float4 tvr[2], wvr[2];
    auto ldg_chunk = [&](int c0) {
        #pragma unroll
        for (int p = 0; p < 2; ++p) {
            const int idx = tid + p * 256;
            const int row = idx >> 3, q = (idx & 7) * 4;
            tvr[p] = *(const float4*)(g_T + ((size_t)b * 256 + k0t + row) * 256
                                      + c0 + q);
            wvr[p] = *(const float4*)(Wv + (size_t)(v0t + row) * 256 + c0 + q);
        }
    };
    auto sts_chunk = [&](int st) {
        float* Ts = sm4 + st * K4_STGF;
        float* Ws = Ts + K4_TILE;
        #pragma unroll
        for (int p = 0; p < 2; ++p) {
            const int idx = tid + p * 256;
            const int row = idx >> 3, q = (idx & 7) * 4;
            Ts[(q + 0) * 68 + row] = tvr[p].x;
            Ts[(q + 1) * 68 + row] = tvr[p].y;
            Ts[(q + 2) * 68 + row] = tvr[p].z;
            Ts[(q + 3) * 68 + row] = tvr[p].w;
            Ws[(q + 0) * 68 + row] = wvr[p].x;
            Ws[(q + 1) * 68 + row] = wvr[p].y;
            Ws[(q + 2) * 68 + row] = wvr[p].z;
            Ws[(q + 3) * 68 + row] = wvr[p].w;
        }
    };

    ldg_chunk(0);
    sts_chunk(0);
    __syncthreads();

    for (int ic = 0; ic < 8; ++ic) {
        if (ic < 7) ldg_chunk((ic + 1) * 32);

        const float* Ts = sm4 + (ic & 1) * K4_STGF;
        const float* Ws = Ts + K4_TILE;
        #pragma unroll
        for (int cc = 0; cc < 32; ++cc) {
            float4 a4 = *(const float4*)(Ts + cc * 68 + ty * 4);
            float4 w4 = *(const float4*)(Ws + cc * 68 + tx * 4);
            unsigned long long w0 = pk2(w4.x, w4.y);
            unsigned long long w1 = pk2(w4.z, w4.w);
            unsigned long long d0 = dup2(a4.x), d1 = dup2(a4.y);
            unsigned long long d2 = dup2(a4.z), d3 = dup2(a4.w);
            fma2(acc[0][0], d0, w0); fma2(acc[0][1], d0, w1);
            fma2(acc[1][0], d1, w0); fma2(acc[1][1], d1, w1);
            fma2(acc[2][0], d2, w0); fma2(acc[2][1], d2, w1);
            fma2(acc[3][0], d3, w0); fma2(acc[3][1], d3, w1);
        }

        if (ic < 7) sts_chunk((ic + 1) & 1);
        __syncthreads();
    }

    #pragma unroll
    for (int i = 0; i < 4; ++i) {
        const int k = k0t + ty * 4 + i;
        const float inv = 1.0f / g_s[b * 256 + k];
        float* dst = out + ((size_t)b * 256 + k) * 256 + v0t + tx * 4;
        float2 p0 = unpk2(acc[i][0]);
        float2 p1 = unpk2(acc[i][1]);
        dst[0] = p0.x * inv + bv[v0t + tx * 4 + 0];
        dst[1] = p0.y * inv + bv[v0t + tx * 4 + 1];
        dst[2] = p1.x * inv + bv[v0t + tx * 4 + 2];
        dst[3] = p1.y * inv + bv[v0t + tx * 4 + 3];
    }
}

// ---------------------------------------------------------------------------
// Launch
// ---------------------------------------------------------------------------
extern "C" void kernel_launch(void* const* d_in, const int* in_sizes, int n_in,
                              void* d_out, int out_size) {
    const float* x  = (const float*)d_in[0];
    const float* Wk = (const float*)d_in[1];
    const float* bk = (const float*)d_in[2];
    const float* Wv = (const float*)d_in[3];
    const float* bv = (const float*)d_in[4];
    float* out = (float*)d_out;

    cudaFuncSetAttribute(k1_gemm, cudaFuncAttributeMaxDynamicSharedMemorySize,
                         K1_SMEM);
    cudaFuncSetAttribute(k3_tmat, cudaFuncAttributeMaxDynamicSharedMemorySize,
                         K3_SMEM);

    k0_prep<<<512, 256>>>(Wk);

    dim3 g1(128, BB);
    k1_gemm<<<g1, 256, K1_SMEM>>>(x, bk);

    dim3 g3(4, 8, BB);
    k3_tmat<<<g3, 256, K3_SMEM>>>();

    dim3 g4(16, BB);
    k4_out<<<g4, 256>>>(Wv, bv, out);
}